// round 11
// baseline (speedup 1.0000x reference)
#include <cuda_runtime.h>
#include <math.h>
#include <stdint.h>

// Problem constants
#define Bc    2
#define Sc    2048
#define Ec    2048
#define Hc    16
#define HDc   128
#define Mrows 4096     // B*S
#define QKV_N 6144     // 3*E
#define GK    2048     // K dim of both GEMMs

// Scratch (device globals: allocation-free per harness rules)
__device__ float g_qkv[(size_t)Mrows * QKV_N];   // ~100 MB
__device__ float g_attn[(size_t)Mrows * Ec];     // ~33 MB

// ---------------------------------------------------------------------------
// Helpers
// ---------------------------------------------------------------------------
__device__ __forceinline__ uint32_t f2tf32(float x) {
    uint32_t r;
    asm("cvt.rna.tf32.f32 %0, %1;" : "=r"(r) : "f"(x));
    return r;
}
__device__ __forceinline__ uint2 split_tf32(float x) {
    uint32_t hi = f2tf32(x);
    uint32_t lo = f2tf32(x - __uint_as_float(hi));
    return make_uint2(hi, lo);
}
__device__ __forceinline__ void mma8(float* c,
                                     uint32_t a0, uint32_t a1, uint32_t a2, uint32_t a3,
                                     uint32_t b0, uint32_t b1) {
    asm volatile(
        "mma.sync.aligned.m16n8k8.row.col.f32.tf32.tf32.f32 "
        "{%0,%1,%2,%3}, {%4,%5,%6,%7}, {%8,%9}, {%0,%1,%2,%3};"
        : "+f"(c[0]), "+f"(c[1]), "+f"(c[2]), "+f"(c[3])
        : "r"(a0), "r"(a1), "r"(a2), "r"(a3), "r"(b0), "r"(b1));
}

// ---------------------------------------------------------------------------
// 3xTF32 tensor-core GEMM (exact R2 kernel — best measured)
// C[M,N] = A[M,K] @ B[N,K]^T + bias[N]
// ---------------------------------------------------------------------------
#define BKg 32
#define SPAD 36

__global__ __launch_bounds__(256)
void gemm_tf32x3(const float* __restrict__ A,
                 const float* __restrict__ Bw,
                 const float* __restrict__ bias,
                 float* __restrict__ C,
                 int Ndim)
{
    extern __shared__ uint2 sm2[];
    uint2* As = sm2;
    uint2* Bs = sm2 + 128 * SPAD;

    const int tid   = threadIdx.x;
    const int lane  = tid & 31;
    const int wid   = tid >> 5;
    const int m_off = (wid & 1) << 6;
    const int n_off = (wid >> 1) << 5;
    const int bm    = blockIdx.y << 7;
    const int bn    = blockIdx.x << 7;

    const int row_base = tid >> 3;
    const int col4     = (tid & 7) << 2;

    float c[4][4][4];
#pragma unroll
    for (int mt = 0; mt < 4; mt++)
#pragma unroll
        for (int nt = 0; nt < 4; nt++)
#pragma unroll
            for (int e = 0; e < 4; e++) c[mt][nt][e] = 0.f;

    float4 pa[4], pb[4];
#pragma unroll
    for (int i = 0; i < 4; i++) {
        int r = row_base + 32 * i;
        pa[i] = *(const float4*)&A [(size_t)(bm + r) * GK + col4];
        pb[i] = *(const float4*)&Bw[(size_t)(bn + r) * GK + col4];
    }

    const int nsteps = GK / BKg;
    for (int step = 0; step < nsteps; step++) {
        __syncthreads();
#pragma unroll
        for (int i = 0; i < 4; i++) {
            int r = row_base + 32 * i;
            float av[4] = {pa[i].x, pa[i].y, pa[i].z, pa[i].w};
            float bv[4] = {pb[i].x, pb[i].y, pb[i].z, pb[i].w};
            uint2 ah[4], bh[4];
#pragma unroll
            for (int j = 0; j < 4; j++) { ah[j] = split_tf32(av[j]); bh[j] = split_tf32(bv[j]); }
            *(uint4*)&As[r * SPAD + col4    ] = make_uint4(ah[0].x, ah[0].y, ah[1].x, ah[1].y);
            *(uint4*)&As[r * SPAD + col4 + 2] = make_uint4(ah[2].x, ah[2].y, ah[3].x, ah[3].y);
            *(uint4*)&Bs[r * SPAD + col4    ] = make_uint4(bh[0].x, bh[0].y, bh[1].x, bh[1].y);
            *(uint4*)&Bs[r * SPAD + col4 + 2] = make_uint4(bh[2].x, bh[2].y, bh[3].x, bh[3].y);
        }
        __syncthreads();

        if (step + 1 < nsteps) {
            int k0 = (step + 1) * BKg;
#pragma unroll
            for (int i = 0; i < 4; i++) {
                int r = row_base + 32 * i;
                pa[i] = *(const float4*)&A [(size_t)(bm + r) * GK + k0 + col4];
                pb[i] = *(const float4*)&Bw[(size_t)(bn + r) * GK + k0 + col4];
            }
        }

#pragma unroll
        for (int kk = 0; kk < 4; kk++) {
            const int kc = (kk << 3) + (lane & 3);
            uint2 a[4][4];
#pragma unroll
            for (int mt = 0; mt < 4; mt++) {
                int r0 = m_off + mt * 16 + (lane >> 2);
                a[mt][0] = As[r0 * SPAD + kc];
                a[mt][1] = As[(r0 + 8) * SPAD + kc];
                a[mt][2] = As[r0 * SPAD + kc + 4];
                a[mt][3] = As[(r0 + 8) * SPAD + kc + 4];
            }
            uint2 b[4][2];
#pragma unroll
            for (int nt = 0; nt < 4; nt++) {
                int n0 = n_off + nt * 8 + (lane >> 2);
                b[nt][0] = Bs[n0 * SPAD + kc];
                b[nt][1] = Bs[n0 * SPAD + kc + 4];
            }
#pragma unroll
            for (int mt = 0; mt < 4; mt++)
#pragma unroll
                for (int nt = 0; nt < 4; nt++) {
                    mma8(c[mt][nt], a[mt][0].x, a[mt][1].x, a[mt][2].x, a[mt][3].x,
                                    b[nt][0].x, b[nt][1].x);
                    mma8(c[mt][nt], a[mt][0].x, a[mt][1].x, a[mt][2].x, a[mt][3].x,
                                    b[nt][0].y, b[nt][1].y);
                    mma8(c[mt][nt], a[mt][0].y, a[mt][1].y, a[mt][2].y, a[mt][3].y,
                                    b[nt][0].x, b[nt][1].x);
                }
        }
    }

#pragma unroll
    for (int mt = 0; mt < 4; mt++) {
        int r0 = bm + m_off + mt * 16 + (lane >> 2);
#pragma unroll
        for (int nt = 0; nt < 4; nt++) {
            int col = bn + n_off + nt * 8 + ((lane & 3) << 1);
            float b0 = bias[col], b1 = bias[col + 1];
            *(float2*)&C[(size_t)r0 * Ndim + col] =
                make_float2(c[mt][nt][0] + b0, c[mt][nt][1] + b1);
            *(float2*)&C[(size_t)(r0 + 8) * Ndim + col] =
                make_float2(c[mt][nt][2] + b0, c[mt][nt][3] + b1);
        }
    }
}

// ---------------------------------------------------------------------------
// Flash attention v5 on mma.sync 3xTF32.
// CTA: 64 q-rows, K-tiles of 64, 256 threads (8 warps).
// Q/K as hi/lo tf32 planes (stride 132 u2); V as fp32 (stride 136 floats,
// split per-fragment in PV — R4-verified); P planes stride 68 u2.
// Smem (uint2 units): Qpl 0 (8448), Kpl 8448 (8448), Vf 16896 (4352 u2 as
// 64x136 floats), Ppl 21248 (64x68=4352), state 25600 (96).
// Total 25696 u2 = 205568 bytes.
// ---------------------------------------------------------------------------
#define QST 132
#define VST 136
#define PST 68
#define FL5_SMEM 205568

__global__ __launch_bounds__(256)
void flash_mma5()
{
    extern __shared__ uint2 sm[];
    uint2* Qpl = sm;
    uint2* Kpl = sm + 8448;
    float* Vf  = (float*)(sm + 16896);
    uint2* Ppl = sm + 21248;
    float* Pf  = (float*)Ppl;          // score view at even float indices
    float* m_s  = (float*)(sm + 25600);
    float* l_s  = m_s + 64;
    float* al_s = m_s + 128;

    const int tid = threadIdx.x, lane = tid & 31, w = tid >> 5;
    const int b = blockIdx.z, h = blockIdx.y;
    const int q0 = blockIdx.x << 6;

    // ---- Load Q (64 x 128), convert to planes ----
    {
        int row = tid >> 2;
        int c0  = (tid & 3) << 5;
        const float* qp = &g_qkv[((size_t)(b*Sc + q0 + row)) * QKV_N + h*384 + c0];
#pragma unroll
        for (int j = 0; j < 8; j++) {
            float4 v = *(const float4*)(qp + 4*j);
            uint2 e0 = split_tf32(v.x), e1 = split_tf32(v.y);
            uint2 e2 = split_tf32(v.z), e3 = split_tf32(v.w);
            *(uint4*)&Qpl[row*QST + c0 + 4*j    ] = make_uint4(e0.x, e0.y, e1.x, e1.y);
            *(uint4*)&Qpl[row*QST + c0 + 4*j + 2] = make_uint4(e2.x, e2.y, e3.x, e3.y);
        }
    }
    if (tid < 64) { m_s[tid] = -INFINITY; l_s[tid] = 0.f; }

    float o[2][4][4];
#pragma unroll
    for (int mt = 0; mt < 2; mt++)
#pragma unroll
        for (int nt = 0; nt < 4; nt++)
#pragma unroll
            for (int e = 0; e < 4; e++) o[mt][nt][e] = 0.f;

    const int qk_m0 = (w & 3) << 4;    // 0,16,32,48
    const int qk_n0 = (w >> 2) << 5;   // 0 or 32
    const int pv_m0 = (w & 1) << 5;    // 0 or 32
    const int pv_n0 = (w >> 1) << 5;   // 0,32,64,96
    const float scale = 11.3137084989847604f;  // HD**0.5 (reference MULTIPLIES)

    const int lrow = tid >> 2;          // loader row 0..63
    const int lc0  = (tid & 3) << 5;    // 0,32,64,96

#pragma unroll 1
    for (int kt = 0; kt < Sc / 64; kt++) {
        // ---- loader: K -> planes, V -> fp32 ----
        {
            const float* kp = &g_qkv[((size_t)(b*Sc + kt*64 + lrow)) * QKV_N
                                     + h*384 + 128 + lc0];
#pragma unroll
            for (int j = 0; j < 8; j++) {
                float4 kv = *(const float4*)(kp + 4*j);
                uint2 k0_ = split_tf32(kv.x), k1_ = split_tf32(kv.y);
                uint2 k2_ = split_tf32(kv.z), k3_ = split_tf32(kv.w);
                *(uint4*)&Kpl[lrow*QST + lc0 + 4*j    ] = make_uint4(k0_.x, k0_.y, k1_.x, k1_.y);
                *(uint4*)&Kpl[lrow*QST + lc0 + 4*j + 2] = make_uint4(k2_.x, k2_.y, k3_.x, k3_.y);
                *(float4*)&Vf[lrow*VST + lc0 + 4*j] = *(const float4*)(kp + 128 + 4*j);
            }
        }
        __syncthreads();

        // ---- S = Q @ K^T (3xTF32), warp tile 16x32 ----
        float sf[4][4];
#pragma unroll
        for (int j = 0; j < 4; j++)
#pragma unroll
            for (int e = 0; e < 4; e++) sf[j][e] = 0.f;

#pragma unroll
        for (int kk = 0; kk < 16; kk++) {
            const int kc = (kk << 3) + (lane & 3);
            const int ar = qk_m0 + (lane >> 2);
            uint2 a0 = Qpl[ar*QST + kc],     a1 = Qpl[(ar+8)*QST + kc];
            uint2 a2 = Qpl[ar*QST + kc + 4], a3 = Qpl[(ar+8)*QST + kc + 4];
#pragma unroll
            for (int j = 0; j < 4; j++) {
                int n0 = qk_n0 + (j << 3) + (lane >> 2);
                uint2 b0 = Kpl[n0*QST + kc], b1 = Kpl[n0*QST + kc + 4];
                mma8(sf[j], a0.x, a1.x, a2.x, a3.x, b0.x, b1.x);
                mma8(sf[j], a0.x, a1.x, a2.x, a3.x, b0.y, b1.y);
                mma8(sf[j], a0.y, a1.y, a2.y, a3.y, b0.x, b1.x);
            }
        }
        {
            int r0 = qk_m0 + (lane >> 2);
            int cc = (lane & 3) << 1;
#pragma unroll
            for (int j = 0; j < 4; j++) {
                int col = qk_n0 + (j << 3) + cc;
                Pf[(r0*PST + col) * 2]         = sf[j][0] * scale;
                Pf[(r0*PST + col + 1) * 2]     = sf[j][1] * scale;
                Pf[((r0+8)*PST + col) * 2]     = sf[j][2] * scale;
                Pf[((r0+8)*PST + col + 1) * 2] = sf[j][3] * scale;
            }
        }
        __syncthreads();

        // ---- online softmax: warp w handles rows 8w..8w+7 (64 cols) ----
#pragma unroll 1
        for (int rr = 0; rr < 8; rr++) {
            int r = (w << 3) + rr;
            float s0 = Pf[(r*PST + lane) * 2];
            float s1 = Pf[(r*PST + 32 + lane) * 2];
            float mx = fmaxf(s0, s1);
#pragma unroll
            for (int off = 16; off > 0; off >>= 1)
                mx = fmaxf(mx, __shfl_xor_sync(0xffffffffu, mx, off));
            float mo = m_s[r];
            float mn = fmaxf(mo, mx);
            float p0 = __expf(s0 - mn);
            float p1 = __expf(s1 - mn);
            float ps = p0 + p1;
#pragma unroll
            for (int off = 16; off > 0; off >>= 1)
                ps += __shfl_xor_sync(0xffffffffu, ps, off);
            Ppl[r*PST + lane]      = split_tf32(p0);
            Ppl[r*PST + 32 + lane] = split_tf32(p1);
            if (lane == 0) {
                float al = (mo == -INFINITY) ? 0.f : __expf(mo - mn);
                al_s[r] = al;
                l_s[r]  = l_s[r]*al + ps;
                m_s[r]  = mn;
            }
        }
        __syncthreads();

        // ---- O = O*alpha + P @ V (3xTF32), warp tile 32x32 ----
#pragma unroll
        for (int mt = 0; mt < 2; mt++) {
            float a0 = al_s[pv_m0 + (mt << 4) + (lane >> 2)];
            float a1 = al_s[pv_m0 + (mt << 4) + 8 + (lane >> 2)];
#pragma unroll
            for (int nt = 0; nt < 4; nt++) {
                o[mt][nt][0] *= a0; o[mt][nt][1] *= a0;
                o[mt][nt][2] *= a1; o[mt][nt][3] *= a1;
            }
        }
#pragma unroll
        for (int kk = 0; kk < 8; kk++) {
            const int kc = (kk << 3) + (lane & 3);
            uint2 ap[2][4];
#pragma unroll
            for (int mt = 0; mt < 2; mt++) {
                int r0 = pv_m0 + (mt << 4) + (lane >> 2);
                ap[mt][0] = Ppl[r0*PST + kc];     ap[mt][1] = Ppl[(r0+8)*PST + kc];
                ap[mt][2] = Ppl[r0*PST + kc + 4]; ap[mt][3] = Ppl[(r0+8)*PST + kc + 4];
            }
#pragma unroll
            for (int nt = 0; nt < 4; nt++) {
                int n0 = pv_n0 + (nt << 3) + (lane >> 2);
                float v0f = Vf[kc*VST + n0];
                float v1f = Vf[(kc + 4)*VST + n0];
                uint32_t vh0 = f2tf32(v0f), vl0 = f2tf32(v0f - __uint_as_float(vh0));
                uint32_t vh1 = f2tf32(v1f), vl1 = f2tf32(v1f - __uint_as_float(vh1));
#pragma unroll
                for (int mt = 0; mt < 2; mt++) {
                    mma8(o[mt][nt], ap[mt][0].x, ap[mt][1].x, ap[mt][2].x, ap[mt][3].x,
                                    vh0, vh1);
                    mma8(o[mt][nt], ap[mt][0].x, ap[mt][1].x, ap[mt][2].x, ap[mt][3].x,
                                    vl0, vl1);
                    mma8(o[mt][nt], ap[mt][0].y, ap[mt][1].y, ap[mt][2].y, ap[mt][3].y,
                                    vh0, vh1);
                }
            }
        }
        __syncthreads();   // K/V/P buffers free for next tile
    }

    // ---- epilogue: normalize by l, write fp32 to g_attn ----
#pragma unroll
    for (int mt = 0; mt < 2; mt++) {
        int r0 = pv_m0 + (mt << 4) + (lane >> 2);
        float i0 = 1.f / l_s[r0];
        float i1 = 1.f / l_s[r0 + 8];
        size_t g0 = ((size_t)(b*Sc + q0 + r0)) * Ec + h*HDc;
        size_t g1 = ((size_t)(b*Sc + q0 + r0 + 8)) * Ec + h*HDc;
#pragma unroll
        for (int nt = 0; nt < 4; nt++) {
            int col = pv_n0 + (nt << 3) + ((lane & 3) << 1);
            *(float2*)&g_attn[g0 + col] = make_float2(o[mt][nt][0]*i0, o[mt][nt][1]*i0);
            *(float2*)&g_attn[g1 + col] = make_float2(o[mt][nt][2]*i1, o[mt][nt][3]*i1);
        }
    }
}

// ---------------------------------------------------------------------------
extern "C" void kernel_launch(void* const* d_in, const int* in_sizes, int n_in,
                              void* d_out, int out_size)
{
    const float* query = (const float*)d_in[0];
    const float* Wqkv  = (const float*)d_in[3];
    const float* bqkv  = (const float*)d_in[4];
    const float* Wproj = (const float*)d_in[5];
    const float* bproj = (const float*)d_in[6];
    float* out = (float*)d_out;

    float *qkvp = nullptr, *attnp = nullptr;
    cudaGetSymbolAddress((void**)&qkvp,  g_qkv);
    cudaGetSymbolAddress((void**)&attnp, g_attn);

    const int gemm_smem = 2 * 128 * SPAD * (int)sizeof(uint2);  // 73728
    cudaFuncSetAttribute(gemm_tf32x3,
                         cudaFuncAttributeMaxDynamicSharedMemorySize, gemm_smem);
    cudaFuncSetAttribute(flash_mma5,
                         cudaFuncAttributeMaxDynamicSharedMemorySize, FL5_SMEM);

    // 1) qkv = query @ Wqkv^T + bqkv
    gemm_tf32x3<<<dim3(QKV_N/128, Mrows/128), 256, gemm_smem>>>(
        query, Wqkv, bqkv, qkvp, QKV_N);

    // 2) flash attention v5 (mma) -> g_attn
    flash_mma5<<<dim3(Sc/64, Hc, Bc), 256, FL5_SMEM>>>();

    // 3) out = attn @ Wproj^T + bproj
    gemm_tf32x3<<<dim3(Ec/128, Mrows/128), 256, gemm_smem>>>(
        attnp, Wproj, bproj, out, Ec);
}

// round 12
// speedup vs baseline: 1.1081x; 1.1081x over previous
#include <cuda_runtime.h>
#include <math.h>
#include <stdint.h>

// Problem constants
#define Bc    2
#define Sc    2048
#define Ec    2048
#define Hc    16
#define HDc   128
#define Mrows 4096     // B*S
#define QKV_N 6144     // 3*E
#define GK    2048     // K dim of both GEMMs

// Scratch (device globals: allocation-free per harness rules)
__device__ float g_qkv[(size_t)Mrows * QKV_N];   // ~100 MB
__device__ float g_attn[(size_t)Mrows * Ec];     // ~33 MB

// ---------------------------------------------------------------------------
// Helpers
// ---------------------------------------------------------------------------
__device__ __forceinline__ uint32_t f2tf32(float x) {
    uint32_t r;
    asm("cvt.rna.tf32.f32 %0, %1;" : "=r"(r) : "f"(x));
    return r;
}
__device__ __forceinline__ uint2 split_tf32(float x) {
    uint32_t hi = f2tf32(x);
    uint32_t lo = f2tf32(x - __uint_as_float(hi));
    return make_uint2(hi, lo);
}
__device__ __forceinline__ void mma8(float* c,
                                     uint32_t a0, uint32_t a1, uint32_t a2, uint32_t a3,
                                     uint32_t b0, uint32_t b1) {
    asm volatile(
        "mma.sync.aligned.m16n8k8.row.col.f32.tf32.tf32.f32 "
        "{%0,%1,%2,%3}, {%4,%5,%6,%7}, {%8,%9}, {%0,%1,%2,%3};"
        : "+f"(c[0]), "+f"(c[1]), "+f"(c[2]), "+f"(c[3])
        : "r"(a0), "r"(a1), "r"(a2), "r"(a3), "r"(b0), "r"(b1));
}

// ---------------------------------------------------------------------------
// 3xTF32 tensor-core GEMM (exact R2 kernel — best measured)
// C[M,N] = A[M,K] @ B[N,K]^T + bias[N]
// ---------------------------------------------------------------------------
#define BKg 32
#define SPAD 36

__global__ __launch_bounds__(256)
void gemm_tf32x3(const float* __restrict__ A,
                 const float* __restrict__ Bw,
                 const float* __restrict__ bias,
                 float* __restrict__ C,
                 int Ndim)
{
    extern __shared__ uint2 sm2[];
    uint2* As = sm2;
    uint2* Bs = sm2 + 128 * SPAD;

    const int tid   = threadIdx.x;
    const int lane  = tid & 31;
    const int wid   = tid >> 5;
    const int m_off = (wid & 1) << 6;
    const int n_off = (wid >> 1) << 5;
    const int bm    = blockIdx.y << 7;
    const int bn    = blockIdx.x << 7;

    const int row_base = tid >> 3;
    const int col4     = (tid & 7) << 2;

    float c[4][4][4];
#pragma unroll
    for (int mt = 0; mt < 4; mt++)
#pragma unroll
        for (int nt = 0; nt < 4; nt++)
#pragma unroll
            for (int e = 0; e < 4; e++) c[mt][nt][e] = 0.f;

    float4 pa[4], pb[4];
#pragma unroll
    for (int i = 0; i < 4; i++) {
        int r = row_base + 32 * i;
        pa[i] = *(const float4*)&A [(size_t)(bm + r) * GK + col4];
        pb[i] = *(const float4*)&Bw[(size_t)(bn + r) * GK + col4];
    }

    const int nsteps = GK / BKg;
    for (int step = 0; step < nsteps; step++) {
        __syncthreads();
#pragma unroll
        for (int i = 0; i < 4; i++) {
            int r = row_base + 32 * i;
            float av[4] = {pa[i].x, pa[i].y, pa[i].z, pa[i].w};
            float bv[4] = {pb[i].x, pb[i].y, pb[i].z, pb[i].w};
            uint2 ah[4], bh[4];
#pragma unroll
            for (int j = 0; j < 4; j++) { ah[j] = split_tf32(av[j]); bh[j] = split_tf32(bv[j]); }
            *(uint4*)&As[r * SPAD + col4    ] = make_uint4(ah[0].x, ah[0].y, ah[1].x, ah[1].y);
            *(uint4*)&As[r * SPAD + col4 + 2] = make_uint4(ah[2].x, ah[2].y, ah[3].x, ah[3].y);
            *(uint4*)&Bs[r * SPAD + col4    ] = make_uint4(bh[0].x, bh[0].y, bh[1].x, bh[1].y);
            *(uint4*)&Bs[r * SPAD + col4 + 2] = make_uint4(bh[2].x, bh[2].y, bh[3].x, bh[3].y);
        }
        __syncthreads();

        if (step + 1 < nsteps) {
            int k0 = (step + 1) * BKg;
#pragma unroll
            for (int i = 0; i < 4; i++) {
                int r = row_base + 32 * i;
                pa[i] = *(const float4*)&A [(size_t)(bm + r) * GK + k0 + col4];
                pb[i] = *(const float4*)&Bw[(size_t)(bn + r) * GK + k0 + col4];
            }
        }

#pragma unroll
        for (int kk = 0; kk < 4; kk++) {
            const int kc = (kk << 3) + (lane & 3);
            uint2 a[4][4];
#pragma unroll
            for (int mt = 0; mt < 4; mt++) {
                int r0 = m_off + mt * 16 + (lane >> 2);
                a[mt][0] = As[r0 * SPAD + kc];
                a[mt][1] = As[(r0 + 8) * SPAD + kc];
                a[mt][2] = As[r0 * SPAD + kc + 4];
                a[mt][3] = As[(r0 + 8) * SPAD + kc + 4];
            }
            uint2 b[4][2];
#pragma unroll
            for (int nt = 0; nt < 4; nt++) {
                int n0 = n_off + nt * 8 + (lane >> 2);
                b[nt][0] = Bs[n0 * SPAD + kc];
                b[nt][1] = Bs[n0 * SPAD + kc + 4];
            }
#pragma unroll
            for (int mt = 0; mt < 4; mt++)
#pragma unroll
                for (int nt = 0; nt < 4; nt++) {
                    mma8(c[mt][nt], a[mt][0].x, a[mt][1].x, a[mt][2].x, a[mt][3].x,
                                    b[nt][0].x, b[nt][1].x);
                    mma8(c[mt][nt], a[mt][0].x, a[mt][1].x, a[mt][2].x, a[mt][3].x,
                                    b[nt][0].y, b[nt][1].y);
                    mma8(c[mt][nt], a[mt][0].y, a[mt][1].y, a[mt][2].y, a[mt][3].y,
                                    b[nt][0].x, b[nt][1].x);
                }
        }
    }

#pragma unroll
    for (int mt = 0; mt < 4; mt++) {
        int r0 = bm + m_off + mt * 16 + (lane >> 2);
#pragma unroll
        for (int nt = 0; nt < 4; nt++) {
            int col = bn + n_off + nt * 8 + ((lane & 3) << 1);
            float b0 = bias[col], b1 = bias[col + 1];
            *(float2*)&C[(size_t)r0 * Ndim + col] =
                make_float2(c[mt][nt][0] + b0, c[mt][nt][1] + b1);
            *(float2*)&C[(size_t)(r0 + 8) * Ndim + col] =
                make_float2(c[mt][nt][2] + b0, c[mt][nt][3] + b1);
        }
    }
}

// ---------------------------------------------------------------------------
// Flash attention, fp32 SIMT, 512 threads (16 warps) in one CTA.
// Same 128-q x 64-k tiling + smem layout as the proven R1 kernel; per-thread
// work halved (QK 4x4, PV 4x8) to double warps/SM for latency hiding.
// ---------------------------------------------------------------------------
#define SQt 128
#define SKt 64
#define DP  132

__global__ __launch_bounds__(512)
void flash_fp32_512()
{
    extern __shared__ float smf[];
    float* Qs   = smf;                    // 128*132
    float* Ks   = Qs  + SQt*DP;           // 64*132
    float* Vs   = Ks  + SKt*DP;           // 64*132
    float* Ps   = Vs  + SKt*DP;           // 128*64
    float* m_s  = Ps  + SQt*SKt;          // 128
    float* l_s  = m_s + SQt;              // 128
    float* al_s = l_s + SQt;              // 128

    const int tid  = threadIdx.x;
    const int lane = tid & 31, w = tid >> 5;   // 16 warps
    const int ty   = tid >> 4, tx  = tid & 15; // 32 x 16
    const int b = blockIdx.z, h = blockIdx.y;
    const int q0 = blockIdx.x << 7;

    const size_t qbase = ((size_t)(b*Sc + q0)) * QKV_N + h*384;

    // Load Q tile (128 x 128): 4096 float4, 512 threads -> 8 each
#pragma unroll
    for (int i = 0; i < 8; i++) {
        int idx = tid + (i << 9);
        int r   = idx >> 5;
        int c4  = (idx & 31) << 2;
        *(float4*)&Qs[r*DP + c4] =
            *(const float4*)&g_qkv[qbase + (size_t)r*QKV_N + c4];
    }
    if (tid < SQt) { m_s[tid] = -INFINITY; l_s[tid] = 0.f; }

    float o[4][8];
#pragma unroll
    for (int i = 0; i < 4; i++)
#pragma unroll
        for (int c = 0; c < 8; c++) o[i][c] = 0.f;

    const float scale = 11.3137084989847604f;  // HD**0.5 (reference MULTIPLIES)

    for (int kt = 0; kt < Sc; kt += SKt) {
        __syncthreads();  // prior PV done with Ks/Vs/Ps; also covers Q/state init
        const size_t kbase = ((size_t)(b*Sc + kt)) * QKV_N + h*384;
        // K/V tiles: 2048 float4 each, 512 threads -> 4 each
#pragma unroll
        for (int i = 0; i < 4; i++) {
            int idx = tid + (i << 9);
            int r   = idx >> 5;
            int c4  = (idx & 31) << 2;
            *(float4*)&Ks[r*DP + c4] =
                *(const float4*)&g_qkv[kbase + (size_t)r*QKV_N + 128 + c4];
            *(float4*)&Vs[r*DP + c4] =
                *(const float4*)&g_qkv[kbase + (size_t)r*QKV_N + 256 + c4];
        }
        __syncthreads();

        // ---- S = Q @ K^T (rows 4*ty+i, cols tx+16c) ----
        float s[4][4];
#pragma unroll
        for (int i = 0; i < 4; i++)
#pragma unroll
            for (int c = 0; c < 4; c++) s[i][c] = 0.f;

#pragma unroll 8
        for (int d = 0; d < HDc; d += 4) {
            float4 kf[4];
#pragma unroll
            for (int c = 0; c < 4; c++)
                kf[c] = *(const float4*)&Ks[(tx + 16*c)*DP + d];
#pragma unroll
            for (int i = 0; i < 4; i++) {
                float4 qf = *(const float4*)&Qs[(4*ty + i)*DP + d];
#pragma unroll
                for (int c = 0; c < 4; c++)
                    s[i][c] += qf.x*kf[c].x + qf.y*kf[c].y
                             + qf.z*kf[c].z + qf.w*kf[c].w;
            }
        }
#pragma unroll
        for (int i = 0; i < 4; i++)
#pragma unroll
            for (int c = 0; c < 4; c++)
                Ps[(4*ty + i)*SKt + tx + 16*c] = s[i][c] * scale;
        __syncthreads();

        // ---- Online softmax: warp w handles rows 8w..8w+7 ----
#pragma unroll 1
        for (int rr = 0; rr < 8; rr++) {
            int r = (w << 3) + rr;
            float s0 = Ps[r*SKt + lane];
            float s1 = Ps[r*SKt + 32 + lane];
            float mx = fmaxf(s0, s1);
#pragma unroll
            for (int off = 16; off > 0; off >>= 1)
                mx = fmaxf(mx, __shfl_xor_sync(0xffffffffu, mx, off));
            float mo = m_s[r];
            float mn = fmaxf(mo, mx);
            float p0 = __expf(s0 - mn);
            float p1 = __expf(s1 - mn);
            float ps = p0 + p1;
#pragma unroll
            for (int off = 16; off > 0; off >>= 1)
                ps += __shfl_xor_sync(0xffffffffu, ps, off);
            Ps[r*SKt + lane]      = p0;
            Ps[r*SKt + 32 + lane] = p1;
            if (lane == 0) {
                float al = (mo == -INFINITY) ? 0.f : __expf(mo - mn);
                al_s[r] = al;
                l_s[r]  = l_s[r]*al + ps;
                m_s[r]  = mn;
            }
        }
        __syncthreads();

        // ---- O = O*alpha + P @ V (rows 4*ty+i, cols tx+16c) ----
        float al[4];
#pragma unroll
        for (int i = 0; i < 4; i++) al[i] = al_s[4*ty + i];
#pragma unroll
        for (int i = 0; i < 4; i++)
#pragma unroll
            for (int c = 0; c < 8; c++) o[i][c] *= al[i];

#pragma unroll 4
        for (int j = 0; j < SKt; j++) {
            float p[4], v[8];
#pragma unroll
            for (int i = 0; i < 4; i++) p[i] = Ps[(4*ty + i)*SKt + j];
#pragma unroll
            for (int c = 0; c < 8; c++) v[c] = Vs[j*DP + tx + 16*c];
#pragma unroll
            for (int i = 0; i < 4; i++)
#pragma unroll
                for (int c = 0; c < 8; c++)
                    o[i][c] += p[i]*v[c];
        }
    }

    // Epilogue: normalize and scatter to (b, s, h*HD + d) layout
#pragma unroll
    for (int i = 0; i < 4; i++) {
        int r = 4*ty + i;
        float inv = 1.0f / l_s[r];
        size_t obase = ((size_t)(b*Sc + q0 + r)) * Ec + h*HDc;
#pragma unroll
        for (int c = 0; c < 8; c++)
            g_attn[obase + tx + 16*c] = o[i][c] * inv;
    }
}

// ---------------------------------------------------------------------------
extern "C" void kernel_launch(void* const* d_in, const int* in_sizes, int n_in,
                              void* d_out, int out_size)
{
    const float* query = (const float*)d_in[0];
    const float* Wqkv  = (const float*)d_in[3];
    const float* bqkv  = (const float*)d_in[4];
    const float* Wproj = (const float*)d_in[5];
    const float* bproj = (const float*)d_in[6];
    float* out = (float*)d_out;

    float *qkvp = nullptr, *attnp = nullptr;
    cudaGetSymbolAddress((void**)&qkvp,  g_qkv);
    cudaGetSymbolAddress((void**)&attnp, g_attn);

    const int gemm_smem = 2 * 128 * SPAD * (int)sizeof(uint2);  // 73728
    cudaFuncSetAttribute(gemm_tf32x3,
                         cudaFuncAttributeMaxDynamicSharedMemorySize, gemm_smem);

    // 1) qkv = query @ Wqkv^T + bqkv
    gemm_tf32x3<<<dim3(QKV_N/128, Mrows/128), 256, gemm_smem>>>(
        query, Wqkv, bqkv, qkvp, QKV_N);

    // 2) flash attention (fp32, 512 threads) -> g_attn
    const int fl_smem = (SQt*DP + 2*SKt*DP + SQt*SKt + 3*SQt) * (int)sizeof(float);
    cudaFuncSetAttribute(flash_fp32_512,
                         cudaFuncAttributeMaxDynamicSharedMemorySize, fl_smem);
    flash_fp32_512<<<dim3(Sc/128, Hc, Bc), 512, fl_smem>>>();

    // 3) out = attn @ Wproj^T + bproj
    gemm_tf32x3<<<dim3(Ec/128, Mrows/128), 256, gemm_smem>>>(
        attnp, Wproj, bproj, out, Ec);
}